// round 2
// baseline (speedup 1.0000x reference)
#include <cuda_runtime.h>
#include <stdint.h>

// out[e,f] = (node_src[src[e],f] + off_src[e,f]) * (node_tgt[tgt[e],f] + off_tgt[e,f])
// F = 256 floats = 64 float4 per edge row.
// edge_ids are int32 (JAX x64 disabled: jnp.int64 request silently becomes int32).

#define FEAT4 64  // 256 / 4

__global__ __launch_bounds__(256) void node_to_edge_kernel(
    const float4* __restrict__ node_src,   // [N, 64] as float4
    const float4* __restrict__ node_tgt,   // [N, 64]
    const int* __restrict__ edge_src_ids,  // [E]
    const int* __restrict__ edge_tgt_ids,  // [E]
    const float4* __restrict__ off_src,    // [E, 64]
    const float4* __restrict__ off_tgt,    // [E, 64]
    float4* __restrict__ out,              // [E, 64]
    long long total4)                      // E * 64
{
    long long idx = (long long)blockIdx.x * blockDim.x + threadIdx.x;
    if (idx >= total4) return;

    long long e  = idx >> 6;        // idx / 64
    int       f4 = (int)(idx & 63); // idx % 64

    long long s = (long long)edge_src_ids[e];
    long long t = (long long)edge_tgt_ids[e];

    float4 a = node_src[s * FEAT4 + f4];
    float4 b = off_src[idx];
    float4 c = node_tgt[t * FEAT4 + f4];
    float4 d = off_tgt[idx];

    float4 r;
    r.x = (a.x + b.x) * (c.x + d.x);
    r.y = (a.y + b.y) * (c.y + d.y);
    r.z = (a.z + b.z) * (c.z + d.z);
    r.w = (a.w + b.w) * (c.w + d.w);

    out[idx] = r;
}

extern "C" void kernel_launch(void* const* d_in, const int* in_sizes, int n_in,
                              void* d_out, int out_size) {
    // metadata order:
    // 0: node_src_feats [N, 256] f32
    // 1: node_tgt_feats [N, 256] f32
    // 2: edge_ids       [2, E]   int32 (see note above)
    // 3: off_edge_src   [E, 256] f32
    // 4: off_edge_tgt   [E, 256] f32
    const float4* node_src = (const float4*)d_in[0];
    const float4* node_tgt = (const float4*)d_in[1];
    const int*    edge_ids = (const int*)d_in[2];
    const float4* off_src  = (const float4*)d_in[3];
    const float4* off_tgt  = (const float4*)d_in[4];
    float4*       out      = (float4*)d_out;

    long long E = (long long)in_sizes[2] / 2;        // edge_ids has 2*E elems
    long long total4 = E * FEAT4;                    // float4 elements of output

    const int* src_ids = edge_ids;                   // row 0
    const int* tgt_ids = edge_ids + E;               // row 1

    int threads = 256;
    long long blocks = (total4 + threads - 1) / threads;
    node_to_edge_kernel<<<(unsigned)blocks, threads>>>(
        node_src, node_tgt, src_ids, tgt_ids, off_src, off_tgt, out, total4);
}

// round 3
// speedup vs baseline: 1.0785x; 1.0785x over previous
#include <cuda_runtime.h>
#include <stdint.h>

// out[e,f] = (node_src[src[e],f] + off_src[e,f]) * (node_tgt[tgt[e],f] + off_tgt[e,f])
// F = 256 floats = 64 float4 per edge row. edge_ids are int32.
//
// Bandwidth strategy: the offset streams and the output are touched exactly
// once -> load/store with .cs (evict-first) so they don't evict the node
// tables (2 x 51 MB, ~6x reuse each) from the ~126 MB L2.

#define FEAT4 64  // 256 / 4

__global__ __launch_bounds__(256) void node_to_edge_kernel(
    const float4* __restrict__ node_src,   // [N, 64] as float4
    const float4* __restrict__ node_tgt,   // [N, 64]
    const int* __restrict__ edge_src_ids,  // [E]
    const int* __restrict__ edge_tgt_ids,  // [E]
    const float4* __restrict__ off_src,    // [E, 64]
    const float4* __restrict__ off_tgt,    // [E, 64]
    float4* __restrict__ out,              // [E, 64]
    long long total4)                      // E * 64
{
    long long idx = (long long)blockIdx.x * blockDim.x + threadIdx.x;
    if (idx >= total4) return;

    long long e  = idx >> 6;        // idx / 64
    int       f4 = (int)(idx & 63); // idx % 64

    long long s = (long long)edge_src_ids[e];
    long long t = (long long)edge_tgt_ids[e];

    // Gathered node rows: default caching (keep resident in L2).
    float4 a = __ldg(&node_src[s * FEAT4 + f4]);
    float4 c = __ldg(&node_tgt[t * FEAT4 + f4]);

    // Single-use streams: evict-first so they don't pollute L2.
    float4 b = __ldcs(&off_src[idx]);
    float4 d = __ldcs(&off_tgt[idx]);

    float4 r;
    r.x = (a.x + b.x) * (c.x + d.x);
    r.y = (a.y + b.y) * (c.y + d.y);
    r.z = (a.z + b.z) * (c.z + d.z);
    r.w = (a.w + b.w) * (c.w + d.w);

    __stcs(&out[idx], r);
}

extern "C" void kernel_launch(void* const* d_in, const int* in_sizes, int n_in,
                              void* d_out, int out_size) {
    // metadata order:
    // 0: node_src_feats [N, 256] f32
    // 1: node_tgt_feats [N, 256] f32
    // 2: edge_ids       [2, E]   int32
    // 3: off_edge_src   [E, 256] f32
    // 4: off_edge_tgt   [E, 256] f32
    const float4* node_src = (const float4*)d_in[0];
    const float4* node_tgt = (const float4*)d_in[1];
    const int*    edge_ids = (const int*)d_in[2];
    const float4* off_src  = (const float4*)d_in[3];
    const float4* off_tgt  = (const float4*)d_in[4];
    float4*       out      = (float4*)d_out;

    long long E = (long long)in_sizes[2] / 2;        // edge_ids has 2*E elems
    long long total4 = E * FEAT4;                    // float4 elements of output

    const int* src_ids = edge_ids;                   // row 0
    const int* tgt_ids = edge_ids + E;               // row 1

    int threads = 256;
    long long blocks = (total4 + threads - 1) / threads;
    node_to_edge_kernel<<<(unsigned)blocks, threads>>>(
        node_src, node_tgt, src_ids, tgt_ids, off_src, off_tgt, out, total4);
}

// round 5
// speedup vs baseline: 1.1052x; 1.0247x over previous
#include <cuda_runtime.h>
#include <stdint.h>

// out[e,f] = (node_src[src[e],f] + off_src[e,f]) * (node_tgt[tgt[e],f] + off_tgt[e,f])
// F = 256 floats. Each thread handles 8 floats (32 B): one v4.b64 evict-last
// node load per table + two float4 evict-first offset loads + two stores.
// edge_ids are int32.
//
// L2 policy:
//   - node tables (2 x 51 MB, ~6x reuse): ld.global.nc.L2::evict_last.v4.b64 -> pin
//   - offset streams + output (922 MB, zero reuse): .cs evict-first -> no pollution
// (ptxas on sm_103 only permits .L2::evict_last on 32-byte loads.)

#define FEAT8 32  // 256 / 8

struct F8 { float4 lo, hi; };

__device__ __forceinline__ F8 ldg_evict_last_32B(const void* p) {
    unsigned long long r0, r1, r2, r3;
    asm volatile("ld.global.nc.L2::evict_last.v4.b64 {%0,%1,%2,%3}, [%4];"
                 : "=l"(r0), "=l"(r1), "=l"(r2), "=l"(r3)
                 : "l"(p));
    F8 v;
    v.lo.x = __uint_as_float((unsigned)(r0));
    v.lo.y = __uint_as_float((unsigned)(r0 >> 32));
    v.lo.z = __uint_as_float((unsigned)(r1));
    v.lo.w = __uint_as_float((unsigned)(r1 >> 32));
    v.hi.x = __uint_as_float((unsigned)(r2));
    v.hi.y = __uint_as_float((unsigned)(r2 >> 32));
    v.hi.z = __uint_as_float((unsigned)(r3));
    v.hi.w = __uint_as_float((unsigned)(r3 >> 32));
    return v;
}

__global__ __launch_bounds__(256) void node_to_edge_kernel(
    const float* __restrict__ node_src,    // [N, 256]
    const float* __restrict__ node_tgt,    // [N, 256]
    const int* __restrict__ edge_src_ids,  // [E]
    const int* __restrict__ edge_tgt_ids,  // [E]
    const float4* __restrict__ off_src,    // [E, 64] as float4
    const float4* __restrict__ off_tgt,    // [E, 64]
    float4* __restrict__ out,              // [E, 64]
    long long total8)                      // E * 32
{
    long long idx = (long long)blockIdx.x * blockDim.x + threadIdx.x;
    if (idx >= total8) return;

    long long e  = idx >> 5;        // idx / 32
    int       f8 = (int)(idx & 31); // 8-float group within row

    long long s = (long long)edge_src_ids[e];
    long long t = (long long)edge_tgt_ids[e];

    // Gathered node rows: 32B loads pinned in L2 (evict-last).
    F8 a = ldg_evict_last_32B(node_src + s * 256 + f8 * 8);
    F8 c = ldg_evict_last_32B(node_tgt + t * 256 + f8 * 8);

    // Single-use streams: evict-first.
    long long q = idx * 2;  // float4 index
    float4 b0 = __ldcs(&off_src[q]);
    float4 b1 = __ldcs(&off_src[q + 1]);
    float4 d0 = __ldcs(&off_tgt[q]);
    float4 d1 = __ldcs(&off_tgt[q + 1]);

    float4 r0, r1;
    r0.x = (a.lo.x + b0.x) * (c.lo.x + d0.x);
    r0.y = (a.lo.y + b0.y) * (c.lo.y + d0.y);
    r0.z = (a.lo.z + b0.z) * (c.lo.z + d0.z);
    r0.w = (a.lo.w + b0.w) * (c.lo.w + d0.w);
    r1.x = (a.hi.x + b1.x) * (c.hi.x + d1.x);
    r1.y = (a.hi.y + b1.y) * (c.hi.y + d1.y);
    r1.z = (a.hi.z + b1.z) * (c.hi.z + d1.z);
    r1.w = (a.hi.w + b1.w) * (c.hi.w + d1.w);

    __stcs(&out[q], r0);
    __stcs(&out[q + 1], r1);
}

extern "C" void kernel_launch(void* const* d_in, const int* in_sizes, int n_in,
                              void* d_out, int out_size) {
    // metadata order:
    // 0: node_src_feats [N, 256] f32
    // 1: node_tgt_feats [N, 256] f32
    // 2: edge_ids       [2, E]   int32
    // 3: off_edge_src   [E, 256] f32
    // 4: off_edge_tgt   [E, 256] f32
    const float*  node_src = (const float*)d_in[0];
    const float*  node_tgt = (const float*)d_in[1];
    const int*    edge_ids = (const int*)d_in[2];
    const float4* off_src  = (const float4*)d_in[3];
    const float4* off_tgt  = (const float4*)d_in[4];
    float4*       out      = (float4*)d_out;

    long long E = (long long)in_sizes[2] / 2;        // edge_ids has 2*E elems
    long long total8 = E * FEAT8;                    // 8-float groups of output

    const int* src_ids = edge_ids;                   // row 0
    const int* tgt_ids = edge_ids + E;               // row 1

    int threads = 256;
    long long blocks = (total8 + threads - 1) / threads;
    node_to_edge_kernel<<<(unsigned)blocks, threads>>>(
        node_src, node_tgt, src_ids, tgt_ids, off_src, off_tgt, out, total8);
}